// round 6
// baseline (speedup 1.0000x reference)
#include <cuda_runtime.h>
#include <cuda_bf16.h>
#include <math.h>

// ---------------------------------------------------------------------------
// NonstationaryGaussianSpectralMixtureKernel
// Phase 1 (per point): u = A*cos(2pi ph), v = A*sin(2pi ph), s2 = s^2,
//   A = w*sqrt(s)*2^(1/4).
// Phase 2: K[i,j] = sum_q (uX uY + vX vY) * r * exp2(d2L*r),
//   r = 1/(s2X+s2Y), d2L = -d2*log2(e).
// r via magic seed + one cubic (Halley) step: err ~ 4e-5.
// Micro-tile 2x4 over 64x32 block tiles -> ~52 regs -> 40 warps/SM.
// ---------------------------------------------------------------------------

#define MAXPTS 8192
// [side][row][point];  row = q (u), 8+q (v), 16+q (s2)
__device__ float g_feat[2][24][MAXPTS];

__device__ __forceinline__ float fex2_fast(float x) {
    float r; asm("ex2.approx.f32 %0, %1;" : "=f"(r) : "f"(x)); return r;
}
// reciprocal: magic seed + 1 cubic step (error ~ 4e-5), 4 fp + 1 alu ops
__device__ __forceinline__ float frcp_cubic(float x) {
    float r0 = __int_as_float(0x7EF311C3 - __float_as_int(x));
    float t  = x * r0;
    float p  = fmaf(t, t, fmaf(-3.0f, t, 3.0f));   // t^2 - 3t + 3
    return r0 * p;
}

__device__ __forceinline__ float selu_f(float x) {
    const float scale = 1.0507009873554805f;
    const float alpha = 1.6732632423543772f;
    return (x > 0.0f) ? scale * x : scale * alpha * expm1f(x);
}
__device__ __forceinline__ float softplus_f(float x) {
    return fmaxf(x, 0.0f) + log1pf(expf(-fabsf(x)));
}

// ---------------------------------------------------------------------------
// Phase 1: 8 threads per point (one per q), 32 points per 256-thread block.
// ---------------------------------------------------------------------------
__global__ void __launch_bounds__(256)
feat_kernel(
    const float* __restrict__ x, const float* __restrict__ y,
    const float* __restrict__ W1, const float* __restrict__ b1,
    const float* __restrict__ Ww, const float* __restrict__ bw,
    const float* __restrict__ Wf, const float* __restrict__ bf,
    const float* __restrict__ Ws, const float* __restrict__ bs,
    int N, int M)
{
    __shared__ float sW1[64 * 3];
    __shared__ float sb1[64];
    __shared__ float sHw[64][9];
    __shared__ float sHs[64][9];
    __shared__ float sHf[64][25];
    __shared__ float sbw[8], sbs[8], sbf[24];
    __shared__ float sh_h[32][65];

    int tid = threadIdx.x;
    for (int i = tid; i < 64 * 3; i += 256) sW1[i] = W1[i];
    for (int i = tid; i < 64;     i += 256) sb1[i] = b1[i];
    for (int i = tid; i < 8 * 64; i += 256) {
        int q = i >> 6, l = i & 63;
        sHw[l][q] = Ww[i];
        sHs[l][q] = Ws[i];
    }
    for (int i = tid; i < 24 * 64; i += 256) {
        int r = i >> 6, l = i & 63;
        sHf[l][r] = Wf[i];
    }
    if (tid < 8)  { sbw[tid] = bw[tid]; sbs[tid] = bs[tid]; }
    if (tid < 24) { sbf[tid] = bf[tid]; }
    __syncthreads();

    int pl    = tid >> 3;
    int lane8 = tid & 7;
    int pg    = blockIdx.x * 32 + pl;
    int total = N + M;

    float P0 = 0.0f, P1 = 0.0f, P2 = 0.0f;
    int side = 0, pt = 0;
    bool valid = (pg < total);
    if (valid) {
        side = (pg < N) ? 0 : 1;
        pt   = (pg < N) ? pg : pg - N;
        const float* P = (pg < N) ? (x + 3 * pg) : (y + 3 * (pg - N));
        P0 = P[0]; P1 = P[1]; P2 = P[2];
    }

    {
        int lbase = lane8 * 8;
#pragma unroll
        for (int k = 0; k < 8; k++) {
            int l = lbase + k;
            float t = sb1[l];
            t = fmaf(sW1[l * 3 + 0], P0, t);
            t = fmaf(sW1[l * 3 + 1], P1, t);
            t = fmaf(sW1[l * 3 + 2], P2, t);
            sh_h[pl][l] = selu_f(t);
        }
    }
    __syncthreads();

    if (!valid) return;

    int q = lane8;
    float aw = sbw[q], as = sbs[q];
    float f0 = sbf[q * 3 + 0], f1 = sbf[q * 3 + 1], f2 = sbf[q * 3 + 2];
#pragma unroll
    for (int l = 0; l < 64; l++) {
        float hl = sh_h[pl][l];
        aw = fmaf(sHw[l][q], hl, aw);
        as = fmaf(sHs[l][q], hl, as);
        f0 = fmaf(sHf[l][q * 3 + 0], hl, f0);
        f1 = fmaf(sHf[l][q * 3 + 1], hl, f1);
        f2 = fmaf(sHf[l][q * 3 + 2], hl, f2);
    }

    float w  = softplus_f(aw);
    float s  = softplus_f(as);
    float g0 = softplus_f(f0);
    float g1 = softplus_f(f1);
    float g2 = softplus_f(f2);
    float phase = g0 * P0 + g1 * P1 + g2 * P2;

    const float TWO_PI  = 6.283185307179586f;
    const float ROOT4_2 = 1.1892071150027210f;  // 2^(1/4)
    float ang = TWO_PI * phase;
    float sv = __sinf(ang);          // MUFU, no slow-path range reduction
    float cv = __cosf(ang);
    float A = w * sqrtf(s) * ROOT4_2;

    g_feat[side][q][pt]      = A * cv;
    g_feat[side][8 + q][pt]  = A * sv;
    g_feat[side][16 + q][pt] = s * s;
}

// ---------------------------------------------------------------------------
// Phase 2: pair kernel. 64(i) x 32(j) tile per 256-thread block,
// 2x4 micro-tile per thread (low regs -> high occupancy).
// ---------------------------------------------------------------------------
__global__ void __launch_bounds__(256)
pair_kernel(const float* __restrict__ x, const float* __restrict__ y,
            float* __restrict__ out, int N, int M)
{
    __shared__ float sfx[24][64];   // x features, 64 i
    __shared__ float sfy[24][32];   // y features, 32 j
    __shared__ float spx[3][64];
    __shared__ float spy[3][32];

    int tid = threadIdx.x;
    int i0 = blockIdx.y * 64;
    int j0 = blockIdx.x * 32;

    // fill
    for (int idx = tid; idx < 24 * 64; idx += 256) {
        int r = idx >> 6, c = idx & 63;
        float pad = (r >= 16) ? 1.0f : 0.0f;
        int gi = i0 + c;
        sfx[r][c] = (gi < N) ? g_feat[0][r][gi] : pad;
    }
    for (int idx = tid; idx < 24 * 32; idx += 256) {
        int r = idx >> 5, c = idx & 31;
        float pad = (r >= 16) ? 1.0f : 0.0f;
        int gj = j0 + c;
        sfy[r][c] = (gj < M) ? g_feat[1][r][gj] : pad;
    }
    for (int idx = tid; idx < 3 * 64; idx += 256) {
        int d = idx >> 6, c = idx & 63;
        int gi = i0 + c;
        spx[d][c] = (gi < N) ? x[gi * 3 + d] : 0.0f;
    }
    for (int idx = tid; idx < 3 * 32; idx += 256) {
        int d = idx >> 5, c = idx & 31;
        int gj = j0 + c;
        spy[d][c] = (gj < M) ? y[gj * 3 + d] : 0.0f;
    }
    __syncthreads();

    int tx = tid & 7;       // j group (8 groups x 4)
    int ty = tid >> 3;      // i group (32 groups x 2)
    int ib = ty * 2;
    int jb = tx * 4;

    const float NLOG2E = -1.4426950408889634f;

    // d2L = -d2*log2e for the 2x4 micro-tile
    float d2L[2][4];
    {
        float2 px0 = *(const float2*)&spx[0][ib];
        float2 px1 = *(const float2*)&spx[1][ib];
        float2 px2 = *(const float2*)&spx[2][ib];
        float4 py0 = *(const float4*)&spy[0][jb];
        float4 py1 = *(const float4*)&spy[1][jb];
        float4 py2 = *(const float4*)&spy[2][jb];

        float xa0[2] = {px0.x, px0.y};
        float xa1[2] = {px1.x, px1.y};
        float xa2[2] = {px2.x, px2.y};
        float ya0[4] = {py0.x, py0.y, py0.z, py0.w};
        float ya1[4] = {py1.x, py1.y, py1.z, py1.w};
        float ya2[4] = {py2.x, py2.y, py2.z, py2.w};

#pragma unroll
        for (int ii = 0; ii < 2; ii++) {
#pragma unroll
            for (int jj = 0; jj < 4; jj++) {
                float dx = xa0[ii] - ya0[jj];
                float dy = xa1[ii] - ya1[jj];
                float dz = xa2[ii] - ya2[jj];
                float d2 = fmaf(dx, dx, fmaf(dy, dy, dz * dz));
                d2L[ii][jj] = d2 * NLOG2E;
            }
        }
    }

    float acc[2][4];
#pragma unroll
    for (int ii = 0; ii < 2; ii++)
#pragma unroll
        for (int jj = 0; jj < 4; jj++) acc[ii][jj] = 0.0f;

#pragma unroll
    for (int q = 0; q < 8; q++) {
        float2 ux2 = *(const float2*)&sfx[q][ib];
        float2 vx2 = *(const float2*)&sfx[8 + q][ib];
        float2 wx2 = *(const float2*)&sfx[16 + q][ib];
        float4 uy4 = *(const float4*)&sfy[q][jb];
        float4 vy4 = *(const float4*)&sfy[8 + q][jb];
        float4 wy4 = *(const float4*)&sfy[16 + q][jb];

        float ux[2] = {ux2.x, ux2.y};
        float vx[2] = {vx2.x, vx2.y};
        float wx[2] = {wx2.x, wx2.y};
        float uy[4] = {uy4.x, uy4.y, uy4.z, uy4.w};
        float vy[4] = {vy4.x, vy4.y, vy4.z, vy4.w};
        float wy[4] = {wy4.x, wy4.y, wy4.z, wy4.w};

#pragma unroll
        for (int ii = 0; ii < 2; ii++) {
#pragma unroll
            for (int jj = 0; jj < 4; jj++) {
                float s2 = wx[ii] + wy[jj];
                float r  = frcp_cubic(s2);               // 4 fp + 1 alu
                float e  = fex2_fast(d2L[ii][jj] * r);   // 1 mul + 1 MUFU
                float cc = fmaf(ux[ii], uy[jj], vx[ii] * vy[jj]);
                float t  = cc * r;                        // independent of e
                acc[ii][jj] = fmaf(t, e, acc[ii][jj]);
            }
        }
    }

    // store: 2 rows x float4
#pragma unroll
    for (int ii = 0; ii < 2; ii++) {
        int i = i0 + ib + ii;
        if (i >= N) continue;
        int j = j0 + jb;
        if (j + 3 < M) {
            float4 v = make_float4(acc[ii][0], acc[ii][1], acc[ii][2], acc[ii][3]);
            *(float4*)&out[(size_t)i * M + j] = v;
        } else {
#pragma unroll
            for (int jj = 0; jj < 4; jj++)
                if (j + jj < M) out[(size_t)i * M + j + jj] = acc[ii][jj];
        }
    }
}

// ---------------------------------------------------------------------------
extern "C" void kernel_launch(void* const* d_in, const int* in_sizes, int n_in,
                              void* d_out, int out_size) {
    const float* x  = (const float*)d_in[0];
    const float* y  = (const float*)d_in[1];
    const float* W1 = (const float*)d_in[2];
    const float* b1 = (const float*)d_in[3];
    const float* Ww = (const float*)d_in[4];
    const float* bw = (const float*)d_in[5];
    const float* Wf = (const float*)d_in[6];
    const float* bf = (const float*)d_in[7];
    const float* Ws = (const float*)d_in[8];
    const float* bs = (const float*)d_in[9];
    float* out = (float*)d_out;

    int N = in_sizes[0] / 3;
    int M = in_sizes[1] / 3;

    int total = N + M;
    feat_kernel<<<(total + 31) / 32, 256>>>(x, y, W1, b1, Ww, bw, Wf, bf,
                                            Ws, bs, N, M);

    dim3 grid((M + 31) / 32, (N + 63) / 64);
    pair_kernel<<<grid, 256>>>(x, y, out, N, M);
}

// round 9
// speedup vs baseline: 1.0741x; 1.0741x over previous
#include <cuda_runtime.h>
#include <cuda_bf16.h>
#include <math.h>

// ---------------------------------------------------------------------------
// NonstationaryGaussianSpectralMixtureKernel
// Phase 1 (per point): u = A*cos(2pi ph), v = A*sin(2pi ph), s2 = s^2,
//   A = w*sqrt(s)*2^(1/4);  also stores coords pre-scaled by sqrt(log2e).
// Phase 2: K[i,j] = sum_q (uX uY + vX vY) * r * exp2(d2L*r),
//   r = 1/(s2X+s2Y), d2L = -|xs-ys|^2  (scaled coords fold the log2e).
// r via magic seed + one cubic (Halley) step (err ~4e-5, validated R5/R6).
// 64x64 tile, 4x4 micro-tile (best measured config, R2/R3).
// ---------------------------------------------------------------------------

#define MAXPTS 8192
// [side][row][point]; rows: q->u, 8+q->v, 16+q->s2, 24..26 -> scaled coords
__device__ float g_feat[2][27][MAXPTS];

__device__ __forceinline__ float fex2_fast(float x) {
    float r; asm("ex2.approx.f32 %0, %1;" : "=f"(r) : "f"(x)); return r;
}
// reciprocal: magic seed + 1 cubic (Halley) step: 4 fp + 1 alu, err ~4e-5
__device__ __forceinline__ float frcp_cubic(float x) {
    float r0 = __int_as_float(0x7EF311C3 - __float_as_int(x));
    float t  = x * r0;
    float p  = fmaf(t, t, fmaf(-3.0f, t, 3.0f));   // t^2 - 3t + 3
    return r0 * p;
}

__device__ __forceinline__ float selu_f(float x) {
    const float scale = 1.0507009873554805f;
    const float alpha = 1.6732632423543772f;
    return (x > 0.0f) ? scale * x : scale * alpha * expm1f(x);
}
__device__ __forceinline__ float softplus_f(float x) {
    return fmaxf(x, 0.0f) + log1pf(expf(-fabsf(x)));
}

// ---------------------------------------------------------------------------
// Phase 1: 8 threads per point (one per q), 32 points per 256-thread block.
// ---------------------------------------------------------------------------
__global__ void __launch_bounds__(256)
feat_kernel(
    const float* __restrict__ x, const float* __restrict__ y,
    const float* __restrict__ W1, const float* __restrict__ b1,
    const float* __restrict__ Ww, const float* __restrict__ bw,
    const float* __restrict__ Wf, const float* __restrict__ bf,
    const float* __restrict__ Ws, const float* __restrict__ bs,
    int N, int M)
{
    __shared__ float sW1[64 * 3];
    __shared__ float sb1[64];
    __shared__ float sHw[64][9];
    __shared__ float sHs[64][9];
    __shared__ float sHf[64][25];
    __shared__ float sbw[8], sbs[8], sbf[24];
    __shared__ float sh_h[32][65];

    int tid = threadIdx.x;
    for (int i = tid; i < 64 * 3; i += 256) sW1[i] = W1[i];
    for (int i = tid; i < 64;     i += 256) sb1[i] = b1[i];
    for (int i = tid; i < 8 * 64; i += 256) {
        int q = i >> 6, l = i & 63;
        sHw[l][q] = Ww[i];
        sHs[l][q] = Ws[i];
    }
    for (int i = tid; i < 24 * 64; i += 256) {
        int r = i >> 6, l = i & 63;
        sHf[l][r] = Wf[i];
    }
    if (tid < 8)  { sbw[tid] = bw[tid]; sbs[tid] = bs[tid]; }
    if (tid < 24) { sbf[tid] = bf[tid]; }
    __syncthreads();

    int pl    = tid >> 3;
    int lane8 = tid & 7;
    int pg    = blockIdx.x * 32 + pl;
    int total = N + M;

    float P0 = 0.0f, P1 = 0.0f, P2 = 0.0f;
    int side = 0, pt = 0;
    bool valid = (pg < total);
    if (valid) {
        side = (pg < N) ? 0 : 1;
        pt   = (pg < N) ? pg : pg - N;
        const float* P = (pg < N) ? (x + 3 * pg) : (y + 3 * (pg - N));
        P0 = P[0]; P1 = P[1]; P2 = P[2];
    }

    {
        int lbase = lane8 * 8;
#pragma unroll
        for (int k = 0; k < 8; k++) {
            int l = lbase + k;
            float t = sb1[l];
            t = fmaf(sW1[l * 3 + 0], P0, t);
            t = fmaf(sW1[l * 3 + 1], P1, t);
            t = fmaf(sW1[l * 3 + 2], P2, t);
            sh_h[pl][l] = selu_f(t);
        }
    }
    __syncthreads();

    if (!valid) return;

    int q = lane8;
    float aw = sbw[q], as = sbs[q];
    float f0 = sbf[q * 3 + 0], f1 = sbf[q * 3 + 1], f2 = sbf[q * 3 + 2];
#pragma unroll
    for (int l = 0; l < 64; l++) {
        float hl = sh_h[pl][l];
        aw = fmaf(sHw[l][q], hl, aw);
        as = fmaf(sHs[l][q], hl, as);
        f0 = fmaf(sHf[l][q * 3 + 0], hl, f0);
        f1 = fmaf(sHf[l][q * 3 + 1], hl, f1);
        f2 = fmaf(sHf[l][q * 3 + 2], hl, f2);
    }

    float w  = softplus_f(aw);
    float s  = softplus_f(as);
    float g0 = softplus_f(f0);
    float g1 = softplus_f(f1);
    float g2 = softplus_f(f2);
    float phase = g0 * P0 + g1 * P1 + g2 * P2;

    const float TWO_PI  = 6.283185307179586f;
    const float ROOT4_2 = 1.1892071150027210f;  // 2^(1/4)
    float ang = TWO_PI * phase;
    float sv = __sinf(ang);
    float cv = __cosf(ang);
    float A = w * sqrtf(s) * ROOT4_2;

    g_feat[side][q][pt]      = A * cv;
    g_feat[side][8 + q][pt]  = A * sv;
    g_feat[side][16 + q][pt] = s * s;

    if (q == 0) {
        const float SQRT_LOG2E = 1.2011224087864498f;  // sqrt(log2(e))
        g_feat[side][24][pt] = P0 * SQRT_LOG2E;
        g_feat[side][25][pt] = P1 * SQRT_LOG2E;
        g_feat[side][26][pt] = P2 * SQRT_LOG2E;
    }
}

// ---------------------------------------------------------------------------
// Phase 2: pair kernel. 64x64 tile per 256-thread block, 4x4 micro-tile.
// ---------------------------------------------------------------------------
__global__ void __launch_bounds__(256)
pair_kernel(float* __restrict__ out, int N, int M)
{
    __shared__ float sfx[27][64];
    __shared__ float sfy[27][64];

    int tid = threadIdx.x;
    int i0 = blockIdx.y * 64;
    int j0 = blockIdx.x * 64;

    for (int idx = tid; idx < 27 * 64; idx += 256) {
        int r = idx >> 6, c = idx & 63;
        float pad = (r >= 16 && r < 24) ? 1.0f : 0.0f;
        int gi = i0 + c;
        sfx[r][c] = (gi < N) ? g_feat[0][r][gi] : pad;
        int gj = j0 + c;
        sfy[r][c] = (gj < M) ? g_feat[1][r][gj] : pad;
    }
    __syncthreads();

    int tx = tid & 15;      // j group
    int ty = tid >> 4;      // i group
    int ib = ty * 4;
    int jb = tx * 4;

    // d2L = -|xs - ys|^2 for the 4x4 micro-tile (log2e folded into coords)
    float d2L[4][4];
    {
        float4 px0 = *(const float4*)&sfx[24][ib];
        float4 px1 = *(const float4*)&sfx[25][ib];
        float4 px2 = *(const float4*)&sfx[26][ib];
        float4 py0 = *(const float4*)&sfy[24][jb];
        float4 py1 = *(const float4*)&sfy[25][jb];
        float4 py2 = *(const float4*)&sfy[26][jb];

        float xa0[4] = {px0.x, px0.y, px0.z, px0.w};
        float xa1[4] = {px1.x, px1.y, px1.z, px1.w};
        float xa2[4] = {px2.x, px2.y, px2.z, px2.w};
        float ya0[4] = {py0.x, py0.y, py0.z, py0.w};
        float ya1[4] = {py1.x, py1.y, py1.z, py1.w};
        float ya2[4] = {py2.x, py2.y, py2.z, py2.w};

#pragma unroll
        for (int ii = 0; ii < 4; ii++) {
#pragma unroll
            for (int jj = 0; jj < 4; jj++) {
                float dx = xa0[ii] - ya0[jj];
                float dy = xa1[ii] - ya1[jj];
                float dz = xa2[ii] - ya2[jj];
                float d2 = fmaf(dx, dx, fmaf(dy, dy, dz * dz));
                d2L[ii][jj] = -d2;
            }
        }
    }

    float acc[4][4];
#pragma unroll
    for (int ii = 0; ii < 4; ii++)
#pragma unroll
        for (int jj = 0; jj < 4; jj++) acc[ii][jj] = 0.0f;

#pragma unroll
    for (int q = 0; q < 8; q++) {
        float4 ux4 = *(const float4*)&sfx[q][ib];
        float4 vx4 = *(const float4*)&sfx[8 + q][ib];
        float4 wx4 = *(const float4*)&sfx[16 + q][ib];
        float4 uy4 = *(const float4*)&sfy[q][jb];
        float4 vy4 = *(const float4*)&sfy[8 + q][jb];
        float4 wy4 = *(const float4*)&sfy[16 + q][jb];

        float ux[4] = {ux4.x, ux4.y, ux4.z, ux4.w};
        float vx[4] = {vx4.x, vx4.y, vx4.z, vx4.w};
        float wx[4] = {wx4.x, wx4.y, wx4.z, wx4.w};
        float uy[4] = {uy4.x, uy4.y, uy4.z, uy4.w};
        float vy[4] = {vy4.x, vy4.y, vy4.z, vy4.w};
        float wy[4] = {wy4.x, wy4.y, wy4.z, wy4.w};

#pragma unroll
        for (int ii = 0; ii < 4; ii++) {
#pragma unroll
            for (int jj = 0; jj < 4; jj++) {
                float s2 = wx[ii] + wy[jj];
                float r  = frcp_cubic(s2);               // 4 fp + 1 alu
                float e  = fex2_fast(d2L[ii][jj] * r);   // 1 mul + 1 MUFU
                float cc = fmaf(ux[ii], uy[jj], vx[ii] * vy[jj]);
                float t  = cc * r;                        // independent of e
                acc[ii][jj] = fmaf(t, e, acc[ii][jj]);
            }
        }
    }

#pragma unroll
    for (int ii = 0; ii < 4; ii++) {
        int i = i0 + ib + ii;
        if (i >= N) continue;
        int j = j0 + jb;
        if (j + 3 < M) {
            float4 v = make_float4(acc[ii][0], acc[ii][1], acc[ii][2], acc[ii][3]);
            *(float4*)&out[(size_t)i * M + j] = v;
        } else {
#pragma unroll
            for (int jj = 0; jj < 4; jj++)
                if (j + jj < M) out[(size_t)i * M + j + jj] = acc[ii][jj];
        }
    }
}

// ---------------------------------------------------------------------------
extern "C" void kernel_launch(void* const* d_in, const int* in_sizes, int n_in,
                              void* d_out, int out_size) {
    const float* x  = (const float*)d_in[0];
    const float* y  = (const float*)d_in[1];
    const float* W1 = (const float*)d_in[2];
    const float* b1 = (const float*)d_in[3];
    const float* Ww = (const float*)d_in[4];
    const float* bw = (const float*)d_in[5];
    const float* Wf = (const float*)d_in[6];
    const float* bf = (const float*)d_in[7];
    const float* Ws = (const float*)d_in[8];
    const float* bs = (const float*)d_in[9];
    float* out = (float*)d_out;

    int N = in_sizes[0] / 3;
    int M = in_sizes[1] / 3;

    int total = N + M;
    feat_kernel<<<(total + 31) / 32, 256>>>(x, y, W1, b1, Ww, bw, Wf, bf,
                                            Ws, bs, N, M);

    dim3 grid((M + 63) / 64, (N + 63) / 64);
    pair_kernel<<<grid, 256>>>(out, N, M);
}